// round 15
// baseline (speedup 1.0000x reference)
#include <cuda_runtime.h>
#include <cuda_bf16.h>
#include <math.h>
#include <stdint.h>

#define NB 4
#define NC 256
#define NH 128
#define NW 128
#define NHW (NH*NW)
#define NINNER 256
#define NHEADS 4
#define NDH 64
#define NS 16
#define NSS 256
#define QT 64
#define GK 256

// -------- scratch --------
__device__ uint32_t g_t1tb[NB*NHW*128];
__device__ uint32_t g_t1ts[NB*NHW*128];
__device__ float    g_qkv [NB*3*NINNER*NHW];
__device__ uint32_t g_kb  [NB*NHEADS*8192];   // permuted fill-order layout
__device__ uint32_t g_ks  [NB*NHEADS*8192];
__device__ uint32_t g_vb  [NB*NHEADS*64*128];
__device__ uint32_t g_vs  [NB*NHEADS*64*128];
__device__ float    g_av  [NB*NINNER*NHW];
__device__ uint32_t g_t2tb[NB*NHW*128];
__device__ uint32_t g_t2ts[NB*NHW*128];
__device__ uint32_t g_w1b [768*128];
__device__ uint32_t g_w1s [768*128];
__device__ uint32_t g_w2b [256*128];
__device__ uint32_t g_w2s [256*128];

// ---- bf16x3 helpers ----
__device__ __forceinline__ void splitpack(float x0, float x1, uint32_t& b, uint32_t& s) {
  __nv_bfloat162 hb = __floats2bfloat162_rn(x0, x1);
  uint32_t bb = *(uint32_t*)&hb;
  float b0 = __uint_as_float(bb << 16);
  float b1 = __uint_as_float(bb & 0xffff0000u);
  __nv_bfloat162 hs = __floats2bfloat162_rn(x0 - b0, x1 - b1);
  b = bb;
  s = *(uint32_t*)&hs;
}
__device__ __forceinline__ void mma16(float* c, const uint32_t* a, const uint32_t* b) {
  asm volatile("mma.sync.aligned.m16n8k16.row.col.f32.bf16.bf16.f32 "
    "{%0,%1,%2,%3}, {%4,%5,%6,%7}, {%8,%9}, {%0,%1,%2,%3};"
    : "+f"(c[0]), "+f"(c[1]), "+f"(c[2]), "+f"(c[3])
    : "r"(a[0]), "r"(a[1]), "r"(a[2]), "r"(a[3]), "r"(b[0]), "r"(b[1]));
}
__device__ __forceinline__ void cpasync16(uint32_t saddr, const void* g) {
  asm volatile("cp.async.ca.shared.global [%0], [%1], 16;" :: "r"(saddr), "l"(g) : "memory");
}

// ============== fused depthwise 3x3 (pad 1) + transpose + bf16x3 split ==============
__global__ void __launch_bounds__(256) dw_t(const float* __restrict__ in,
                                            const float* __restrict__ wt,
                                            uint32_t* __restrict__ outb,
                                            uint32_t* __restrict__ outs) {
  __shared__ float t[32][33];
  int hw0 = blockIdx.x*32, c0 = blockIdx.y*32, b = blockIdx.z;
  int tx = threadIdx.x & 31, ty = threadIdx.x >> 5;
  int x = (hw0 + tx) & (NW-1), y = (hw0 + tx) >> 7;
  #pragma unroll
  for (int r = 0; r < 4; r++) {
    int c = c0 + ty + r*8;
    const float* wp = wt + c*9;
    const float* ip = in + ((size_t)b*256 + c)*NHW;
    float s = 0.f;
    #pragma unroll
    for (int dy = -1; dy <= 1; dy++) {
      int yy = y + dy;
      if ((unsigned)yy >= NH) continue;
      #pragma unroll
      for (int dx = -1; dx <= 1; dx++) {
        int xx = x + dx;
        if ((unsigned)xx >= NW) continue;
        s = fmaf(ip[yy*NW+xx], wp[(dy+1)*3 + dx+1], s);
      }
    }
    t[ty + r*8][tx] = s;
  }
  __syncthreads();
  #pragma unroll
  for (int e0 = 0; e0 < 2; e0++) {
    int e = e0*256 + threadIdx.x;
    int pp = e & 15, hwl = e >> 4;
    uint32_t pb, ps;
    splitpack(t[2*pp][hwl], t[2*pp+1][hwl], pb, ps);
    size_t o = ((size_t)b*NHW + hw0 + hwl)*128 + (c0 >> 1) + pp;
    outb[o] = pb;
    outs[o] = ps;
  }
}

// ============== weight pre-split ==============
__global__ void wsplit(const float* __restrict__ w, uint32_t* __restrict__ wb,
                       uint32_t* __restrict__ ws_, int n) {
  int e = blockIdx.x*256 + threadIdx.x;
  if (e < n) {
    int m = e >> 7, cp = e & 127;
    splitpack(w[m*256 + 2*cp], w[m*256 + 2*cp + 1], wb[e], ws_[e]);
  }
}

// ======================= bf16x3 mma.sync GEMM, cp.async double-buffered =======================
#define GP 20
#define MMSTG 10240    // words per stage (4 arrays x 2560)
__global__ void __launch_bounds__(256, 2) mm_bf16(const uint32_t* __restrict__ Ab,
                                                  const uint32_t* __restrict__ As,
                                                  const uint32_t* __restrict__ Btb,
                                                  const uint32_t* __restrict__ Bts,
                                                  float* __restrict__ C, int M) {
  extern __shared__ uint32_t sh[];
  const int tid = threadIdx.x;
  const int wid = tid >> 5, lane = tid & 31;
  const int wm = wid >> 2, wn = wid & 3;
  const int g = lane >> 2, tg = lane & 3;
  const int n0 = blockIdx.x * 128;
  const int m0 = blockIdx.y * 128;
  const int bz = blockIdx.z;

  const uint32_t* Ab0 = Ab + (size_t)m0*128;
  const uint32_t* As0 = As + (size_t)m0*128;
  const uint32_t* Bb0 = Btb + ((size_t)bz*NHW + n0)*128;
  const uint32_t* Bs0 = Bts + ((size_t)bz*NHW + n0)*128;

  uint32_t sbase;
  asm("{ .reg .u64 t; cvta.to.shared.u64 t, %1; cvt.u32.u64 %0, t; }"
      : "=r"(sbase) : "l"(sh));

  // per-thread fill coordinates (2 units of 16B per array per chunk)
  const int r0 = tid >> 2, c40 = tid & 3;              // e = tid
  const int r1 = (256 + tid) >> 2, c41 = tid & 3;      // e = 256 + tid

  float acc[4][4][4];
  #pragma unroll
  for (int i=0;i<4;i++)
    #pragma unroll
    for (int j=0;j<4;j++)
      #pragma unroll
      for (int l=0;l<4;l++) acc[i][j][l] = 0.f;

  // ---- issue chunk 0 into stage 0 ----
  {
    uint32_t sb = sbase;
    uint32_t so0 = (uint32_t)(r0*GP + c40*4)*4, so1 = (uint32_t)(r1*GP + c41*4)*4;
    size_t go0 = (size_t)r0*128 + c40*4, go1 = (size_t)r1*128 + c41*4;
    cpasync16(sb + so0,           Ab0 + go0);
    cpasync16(sb + so1,           Ab0 + go1);
    cpasync16(sb + 2560*4 + so0,  As0 + go0);
    cpasync16(sb + 2560*4 + so1,  As0 + go1);
    cpasync16(sb + 5120*4 + so0,  Bb0 + go0);
    cpasync16(sb + 5120*4 + so1,  Bb0 + go1);
    cpasync16(sb + 7680*4 + so0,  Bs0 + go0);
    cpasync16(sb + 7680*4 + so1,  Bs0 + go1);
    asm volatile("cp.async.commit_group;" ::: "memory");
  }

  for (int chunk = 0; chunk < 8; chunk++) {
    // issue chunk+1 into the other stage
    if (chunk < 7) {
      int kcp = (chunk + 1) * 16;
      uint32_t sb = sbase + ((chunk + 1) & 1) * (MMSTG*4);
      uint32_t so0 = (uint32_t)(r0*GP + c40*4)*4, so1 = (uint32_t)(r1*GP + c41*4)*4;
      size_t go0 = (size_t)r0*128 + kcp + c40*4, go1 = (size_t)r1*128 + kcp + c41*4;
      cpasync16(sb + so0,           Ab0 + go0);
      cpasync16(sb + so1,           Ab0 + go1);
      cpasync16(sb + 2560*4 + so0,  As0 + go0);
      cpasync16(sb + 2560*4 + so1,  As0 + go1);
      cpasync16(sb + 5120*4 + so0,  Bb0 + go0);
      cpasync16(sb + 5120*4 + so1,  Bb0 + go1);
      cpasync16(sb + 7680*4 + so0,  Bs0 + go0);
      cpasync16(sb + 7680*4 + so1,  Bs0 + go1);
      asm volatile("cp.async.commit_group;" ::: "memory");
      asm volatile("cp.async.wait_group 1;" ::: "memory");
    } else {
      asm volatile("cp.async.wait_group 0;" ::: "memory");
    }
    __syncthreads();

    const uint32_t* sAb = sh + (chunk & 1) * MMSTG;
    const uint32_t* sAs = sAb + 2560;
    const uint32_t* sBb = sAb + 5120;
    const uint32_t* sBs = sAb + 7680;

    #pragma unroll
    for (int ks = 0; ks < 2; ks++) {
      int k0 = ks*8;
      uint32_t bb[4][2], bs[4][2];
      #pragma unroll
      for (int nt = 0; nt < 4; nt++) {
        int n = wn*32 + nt*8 + g;
        bb[nt][0] = sBb[n*GP + k0 + tg];
        bb[nt][1] = sBb[n*GP + k0 + tg + 4];
        bs[nt][0] = sBs[n*GP + k0 + tg];
        bs[nt][1] = sBs[n*GP + k0 + tg + 4];
      }
      #pragma unroll
      for (int mt = 0; mt < 4; mt++) {
        int m = wm*64 + mt*16 + g;
        uint32_t ab[4], as_[4];
        ab[0]  = sAb[m*GP + k0 + tg];
        ab[1]  = sAb[(m+8)*GP + k0 + tg];
        ab[2]  = sAb[m*GP + k0 + tg + 4];
        ab[3]  = sAb[(m+8)*GP + k0 + tg + 4];
        as_[0] = sAs[m*GP + k0 + tg];
        as_[1] = sAs[(m+8)*GP + k0 + tg];
        as_[2] = sAs[m*GP + k0 + tg + 4];
        as_[3] = sAs[(m+8)*GP + k0 + tg + 4];
        #pragma unroll
        for (int nt = 0; nt < 4; nt++) {
          mma16(acc[mt][nt], ab,  bb[nt]);
          mma16(acc[mt][nt], ab,  bs[nt]);
          mma16(acc[mt][nt], as_, bb[nt]);
        }
      }
    }
    __syncthreads();
  }

  float* Cb = C + (size_t)bz*M*NHW;
  #pragma unroll
  for (int mt = 0; mt < 4; mt++) {
    int row = m0 + wm*64 + mt*16 + g;
    #pragma unroll
    for (int nt = 0; nt < 4; nt++) {
      int col = n0 + wn*32 + nt*8 + 2*tg;
      *(float2*)(Cb + (size_t)row*NHW + col) =
          make_float2(acc[mt][nt][0], acc[mt][nt][1]);
      *(float2*)(Cb + (size_t)(row+8)*NHW + col) =
          make_float2(acc[mt][nt][2], acc[mt][nt][3]);
    }
  }
}

// ======================= 8x8 max pool + bf16x3 split =======================
__global__ void pool_split(const float* __restrict__ qkv,
                           uint32_t* __restrict__ kb, uint32_t* __restrict__ ks_,
                           uint32_t* __restrict__ vb, uint32_t* __restrict__ vs_) {
  int idx = blockIdx.x*256 + threadIdx.x;   // 0..262143
  int which = idx >> 17;
  int r = idx & 131071;
  int bh = r >> 13;
  int b = bh >> 2, head = bh & 3;
  if (which == 0) {
    int rem = r & 8191;
    int u = rem >> 5, lane = rem & 31;
    int j  = ((u >> 3) << 3) | (lane >> 2);
    int dp = ((u & 7) << 2) | (lane & 3);
    int oh = j >> 4, ow = j & 15;
    const float* p0 = qkv + ((size_t)(b*768 + 256 + 8*dp + head))*NHW + (oh*8)*NW + ow*8;
    const float* p1 = p0 + (size_t)4*NHW;
    float m0 = -1e30f, m1 = -1e30f;
    #pragma unroll
    for (int i = 0; i < 8; i++)
      #pragma unroll
      for (int jj = 0; jj < 8; jj++) {
        m0 = fmaxf(m0, p0[i*NW+jj]);
        m1 = fmaxf(m1, p1[i*NW+jj]);
      }
    splitpack(m0, m1, kb[r], ks_[r]);
  } else {
    int d = (r >> 7) & 63, jp = r & 127;
    int j0 = 2*jp;
    int oh = j0 >> 4, ow = j0 & 15;
    const float* p = qkv + ((size_t)(b*768 + 512 + 4*d + head))*NHW + (oh*8)*NW + ow*8;
    float m0 = -1e30f, m1 = -1e30f;
    #pragma unroll
    for (int i = 0; i < 8; i++)
      #pragma unroll
      for (int jj = 0; jj < 8; jj++) {
        m0 = fmaxf(m0, p[i*NW+jj]);
        m1 = fmaxf(m1, p[i*NW+8+jj]);
      }
    splitpack(m0, m1, vb[r], vs_[r]);
  }
}

// ======================= fused bf16x3 attention, QT=64, fused softmax =======================
#define SSTR 260
#define KPP 36
#define QPP 36
#define RPP 36
#define PPP 132
#define VPP 68
#define LSTR 68
#define OSTR 66

__global__ void __launch_bounds__(256) attn_k(
    const float* __restrict__ qkv,
    const uint32_t* __restrict__ kb, const uint32_t* __restrict__ ks_,
    const uint32_t* __restrict__ vb, const uint32_t* __restrict__ vs_,
    const float* __restrict__ relw, const float* __restrict__ relh,
    float* __restrict__ attn_out, float* __restrict__ av) {
  extern __shared__ float smf[];
  uint32_t* smu = (uint32_t*)smf;
  float*    sS  = smf;                    // 16640
  uint32_t* sKb = smu + 16640;            // 9216
  uint32_t* sKs = smu + 25856;            // 9216
  uint32_t* sQb = smu + 35072;            // 2304
  uint32_t* sQs = smu + 37376;            // 2304
  uint32_t* sRb = smu + 39680;            // 2304
  uint32_t* sRs = smu + 41984;            // 2304
  float*    sL  = smf + 44288;            // 4352
  float*    sM  = smf + 48640;            // 512
  float*    sInv= smf + 49152;            // 64
  uint32_t* sPb = sKb;                    // P overlays K
  uint32_t* sPs = sKs;
  uint32_t* sVb = smu + 35072;            // V halves overlay Q+R
  uint32_t* sVs = smu + 39424;
  float*    sO  = smf;                    // out overlays sS

  const int tid = threadIdx.x;
  const int wid = tid >> 5, lane = tid & 31;
  const int g = lane >> 2, tg = lane & 3;
  const int head = blockIdx.y;
  const int b = blockIdx.z;
  const int i0 = blockIdx.x*QT;
  const int hq = i0 >> 7;
  const int w0 = i0 & (NW-1);
  const int h8 = hq >> 3;

  // ---- load Q, split+pack: unit pattern (g -> qi-in-8, tg -> dp-in-4), bank 4g+tg ----
  #pragma unroll
  for (int it = 0; it < 8; it++) {
    int u = it*8 + wid;               // 0..63
    int qi = (u >> 3)*8 + g;
    int dp = (u & 7)*4 + tg;
    float x0 = qkv[((size_t)(b*768) + 8*dp + head)*NHW + i0 + qi];
    float x1 = qkv[((size_t)(b*768) + 8*dp + 4 + head)*NHW + i0 + qi];
    splitpack(x0, x1, sQb[qi*QPP + dp], sQs[qi*QPP + dp]);
  }
  // ---- rel tables padded to 64 rows: 0..30 relh, 32..62 relw (same unit pattern) ----
  #pragma unroll
  for (int it = 0; it < 8; it++) {
    int u = it*8 + wid;
    int n  = (u >> 3)*8 + g;
    int dp = (u & 7)*4 + tg;
    float x0 = 0.f, x1 = 0.f;
    if (n < 31)                 { x0 = relh[n*64 + 2*dp];      x1 = relh[n*64 + 2*dp + 1]; }
    else if (n >= 32 && n < 63) { x0 = relw[(n-32)*64 + 2*dp]; x1 = relw[(n-32)*64 + 2*dp + 1]; }
    splitpack(x0, x1, sRb[n*RPP + dp], sRs[n*RPP + dp]);
  }
  // ---- load pre-split K from permuted gmem layout (coalesced + conflict-free) ----
  {
    const uint32_t* kbp = kb  + (size_t)(b*NHEADS + head)*8192;
    const uint32_t* ksp = ks_ + (size_t)(b*NHEADS + head)*8192;
    #pragma unroll 8
    for (int it = 0; it < 32; it++) {
      int u = it*8 + wid;             // 0..255
      int j  = (u >> 3)*8 + g;
      int dp = (u & 7)*4 + tg;
      sKb[j*KPP + dp] = kbp[u*32 + lane];
      sKs[j*KPP + dp] = ksp[u*32 + lane];
    }
  }
  __syncthreads();

  // ================= QK scores (acc stays in regs) =================
  const int n0w = wid*32;
  float acc[4][4][4];
  #pragma unroll
  for (int i=0;i<4;i++)
    #pragma unroll
    for (int j=0;j<4;j++)
      #pragma unroll
      for (int l=0;l<4;l++) acc[i][j][l]=0.f;
  #pragma unroll
  for (int ks = 0; ks < 4; ks++) {
    int k0 = ks*8;
    uint32_t bb[4][2], bs[4][2];
    #pragma unroll
    for (int nt = 0; nt < 4; nt++) {
      int j = n0w + nt*8 + g;
      bb[nt][0] = sKb[j*KPP + k0 + tg];
      bb[nt][1] = sKb[j*KPP + k0 + tg + 4];
      bs[nt][0] = sKs[j*KPP + k0 + tg];
      bs[nt][1] = sKs[j*KPP + k0 + tg + 4];
    }
    #pragma unroll
    for (int mt = 0; mt < 4; mt++) {
      int q = mt*16 + g;
      uint32_t ab[4], as_[4];
      ab[0]  = sQb[q*QPP + k0 + tg];
      ab[1]  = sQb[(q+8)*QPP + k0 + tg];
      ab[2]  = sQb[q*QPP + k0 + tg + 4];
      ab[3]  = sQb[(q+8)*QPP + k0 + tg + 4];
      as_[0] = sQs[q*QPP + k0 + tg];
      as_[1] = sQs[(q+8)*QPP + k0 + tg];
      as_[2] = sQs[q*QPP + k0 + tg + 4];
      as_[3] = sQs[(q+8)*QPP + k0 + tg + 4];
      #pragma unroll
      for (int nt = 0; nt < 4; nt++) {
        mma16(acc[mt][nt], ab,  bb[nt]);
        mma16(acc[mt][nt], ab,  bs[nt]);
        mma16(acc[mt][nt], as_, bb[nt]);
      }
    }
  }
  // ================= bias logits (64 x 64, warp = 8 cols) =================
  {
    float acc2[4][4];
    #pragma unroll
    for (int i=0;i<4;i++)
      #pragma unroll
      for (int l=0;l<4;l++) acc2[i][l]=0.f;
    #pragma unroll
    for (int ks = 0; ks < 4; ks++) {
      int k0 = ks*8;
      int n = wid*8 + g;
      uint32_t bb[2], bs[2];
      bb[0] = sRb[n*RPP + k0 + tg];
      bb[1] = sRb[n*RPP + k0 + tg + 4];
      bs[0] = sRs[n*RPP + k0 + tg];
      bs[1] = sRs[n*RPP + k0 + tg + 4];
      #pragma unroll
      for (int mt = 0; mt < 4; mt++) {
        int q = mt*16 + g;
        uint32_t ab[4], as_[4];
        ab[0]  = sQb[q*QPP + k0 + tg];
        ab[1]  = sQb[(q+8)*QPP + k0 + tg];
        ab[2]  = sQb[q*QPP + k0 + tg + 4];
        ab[3]  = sQb[(q+8)*QPP + k0 + tg + 4];
        as_[0] = sQs[q*QPP + k0 + tg];
        as_[1] = sQs[(q+8)*QPP + k0 + tg];
        as_[2] = sQs[q*QPP + k0 + tg + 4];
        as_[3] = sQs[(q+8)*QPP + k0 + tg + 4];
        mma16(acc2[mt], ab,  bb);
        mma16(acc2[mt], ab,  bs);
        mma16(acc2[mt], as_, bb);
      }
    }
    #pragma unroll
    for (int mt = 0; mt < 4; mt++) {
      int q = mt*16 + g;
      int col = wid*8 + 2*tg;
      *(float2*)&sL[q*LSTR + col]     = make_float2(acc2[mt][0], acc2[mt][1]);
      *(float2*)&sL[(q+8)*LSTR + col] = make_float2(acc2[mt][2], acc2[mt][3]);
    }
  }
  __syncthreads();

  // ======= QK epilogue: add bias, scale, store scores, row-max partials =======
  #pragma unroll
  for (int mt = 0; mt < 4; mt++) {
    #pragma unroll
    for (int rr = 0; rr < 2; rr++) {
      int qq = mt*16 + rr*8 + g;
      const float* lrow = sL + qq*LSTR;
      const int w8 = (w0 + qq) >> 3;
      float mxv = -1e30f;
      #pragma unroll
      for (int nt = 0; nt < 4; nt++) {
        int col = n0w + nt*8 + 2*tg;
        float lh  = lrow[(col >> 4) - h8 + 15];
        float lw0 = lrow[32 + (col & 15) - w8 + 15];
        float lw1 = lrow[32 + ((col+1) & 15) - w8 + 15];
        float s0 = (acc[mt][nt][rr*2+0] + lh + lw0) * 0.125f;
        float s1 = (acc[mt][nt][rr*2+1] + lh + lw1) * 0.125f;
        *(float2*)&sS[qq*SSTR + col] = make_float2(s0, s1);
        mxv = fmaxf(mxv, fmaxf(s0, s1));
      }
      mxv = fmaxf(mxv, __shfl_xor_sync(0xffffffffu, mxv, 1));
      mxv = fmaxf(mxv, __shfl_xor_sync(0xffffffffu, mxv, 2));
      if (tg == 0) sM[qq*8 + wid] = mxv;
    }
  }
  __syncthreads();

  // ======= exp + sum in one pass (4 threads/query); V half 0 load =======
  {
    const int q = tid >> 2, l4 = tid & 3;
    float* srow = sS + q*SSTR;
    float mx = sM[q*8];
    #pragma unroll
    for (int w = 1; w < 8; w++) mx = fmaxf(mx, sM[q*8 + w]);
    float sum = 0.f;
    #pragma unroll
    for (int i = 0; i < 64; i++) {
      int j = i*4 + l4;
      float e2 = __expf(srow[j] - mx);
      srow[j] = e2;
      sum += e2;
    }
    sum += __shfl_xor_sync(0xffffffffu, sum, 1);
    sum += __shfl_xor_sync(0xffffffffu, sum, 2);
    if (l4 == 0) sInv[q] = 1.f / sum;
  }
  {
    const uint32_t* vbp = vb  + ((size_t)(b*NHEADS + head)*64)*128;
    const uint32_t* vsp = vs_ + ((size_t)(b*NHEADS + head)*64)*128;
    #pragma unroll
    for (int it = 0; it < 16; it++) {
      int e = it*256 + tid;
      int d = e >> 6, jp = e & 63;
      sVb[d*VPP + jp] = vbp[d*128 + jp];
      sVs[d*VPP + jp] = vsp[d*128 + jp];
    }
  }
  __syncthreads();

  // ======= attn write (normalized) + P split into dead K region =======
  float* aout = attn_out + ((size_t)(b*NHEADS + head)*NHW + i0)*NSS;
  #pragma unroll 4
  for (int it = 0; it < 32; it++) {
    int e = it*256 + tid;
    int qi = e >> 7, jp = e & 127;
    float inv = sInv[qi];
    float2 p2 = *(const float2*)&sS[qi*SSTR + 2*jp];
    p2.x *= inv; p2.y *= inv;
    *(float2*)&aout[(size_t)qi*NSS + 2*jp] = p2;
    splitpack(p2.x, p2.y, sPb[qi*PPP + jp], sPs[qi*PPP + jp]);
  }
  __syncthreads();

  // ================= AV (two j-halves) =================
  {
    const int wm = wid >> 2, wn = wid & 3;   // 2 x 4
    float acc3[2][2][4];
    #pragma unroll
    for (int i=0;i<2;i++)
      #pragma unroll
      for (int j=0;j<2;j++)
        #pragma unroll
        for (int l=0;l<4;l++) acc3[i][j][l]=0.f;

    #pragma unroll 1
    for (int half = 0; half < 2; half++) {
      if (half == 1) {
        __syncthreads();
        const uint32_t* vbp = vb  + ((size_t)(b*NHEADS + head)*64)*128 + 64;
        const uint32_t* vsp = vs_ + ((size_t)(b*NHEADS + head)*64)*128 + 64;
        #pragma unroll
        for (int it = 0; it < 16; it++) {
          int e = it*256 + tid;
          int d = e >> 6, jp = e & 63;
          sVb[d*VPP + jp] = vbp[d*128 + jp];
          sVs[d*VPP + jp] = vsp[d*128 + jp];
        }
        __syncthreads();
      }
      const int p0 = half*64;
      #pragma unroll 4
      for (int ks = 0; ks < 8; ks++) {
        int k0 = ks*8;
        uint32_t ab[2][4], as_[2][4];
        #pragma unroll
        for (int mt = 0; mt < 2; mt++) {
          int q = wm*32 + mt*16 + g;
          ab[mt][0]  = sPb[q*PPP + p0 + k0 + tg];
          ab[mt][1]  = sPb[(q+8)*PPP + p0 + k0 + tg];
          ab[mt][2]  = sPb[q*PPP + p0 + k0 + tg + 4];
          ab[mt][3]  = sPb[(q+8)*PPP + p0 + k0 + tg + 4];
          as_[mt][0] = sPs[q*PPP + p0 + k0 + tg];
          as_[mt][1] = sPs[(q+8)*PPP + p0 + k0 + tg];
          as_[mt][2] = sPs[q*PPP + p0 + k0 + tg + 4];
          as_[mt][3] = sPs[(q+8)*PPP + p0 + k0 + tg + 4];
        }
        uint32_t bb[2][2], bs[2][2];
        #pragma unroll
        for (int nt = 0; nt < 2; nt++) {
          int d = wn*16 + nt*8 + g;
          bb[nt][0] = sVb[d*VPP + k0 + tg];
          bb[nt][1] = sVb[d*VPP + k0 + tg + 4];
          bs[nt][0] = sVs[d*VPP + k0 + tg];
          bs[nt][1] = sVs[d*VPP + k0 + tg + 4];
        }
        #pragma unroll
        for (int mt = 0; mt < 2; mt++)
          #pragma unroll
          for (int nt = 0; nt < 2; nt++) {
            mma16(acc3[mt][nt], ab[mt],  bb[nt]);
            mma16(acc3[mt][nt], ab[mt],  bs[nt]);
            mma16(acc3[mt][nt], as_[mt], bb[nt]);
          }
      }
    }
    #pragma unroll
    for (int mt = 0; mt < 2; mt++) {
      int q = wm*32 + mt*16 + g;
      #pragma unroll
      for (int nt = 0; nt < 2; nt++) {
        int col = wn*16 + nt*8 + 2*tg;
        *(float2*)&sO[q*OSTR + col]     = make_float2(acc3[mt][nt][0], acc3[mt][nt][1]);
        *(float2*)&sO[(q+8)*OSTR + col] = make_float2(acc3[mt][nt][2], acc3[mt][nt][3]);
      }
    }
  }
  __syncthreads();
  #pragma unroll
  for (int l = 0; l < 16; l++) {
    int e = l*256 + tid;
    int d = e >> 6, qi = e & 63;
    av[((size_t)(b*NINNER) + d*NHEADS + head)*NHW + i0 + qi] = sO[qi*OSTR + d];
  }
}

// ======================= launch =======================
extern "C" void kernel_launch(void* const* d_in, const int* in_sizes, int n_in,
                              void* d_out, int out_size) {
  const float* x    = (const float*)d_in[0];
  const float* dw1  = (const float*)d_in[1];
  const float* pw1  = (const float*)d_in[2];
  const float* relw = (const float*)d_in[3];
  const float* relh = (const float*)d_in[4];
  const float* dw2  = (const float*)d_in[5];
  const float* pw2  = (const float*)d_in[6];

  float* out  = (float*)d_out;
  float* attn = out + (size_t)NB*NINNER*NHW;

  uint32_t *t1tb, *t1ts, *t2tb, *t2ts, *kb, *ks, *vb, *vs;
  uint32_t *w1b, *w1s, *w2b, *w2s;
  float *qkvb, *avb;
  cudaGetSymbolAddress((void**)&t1tb, g_t1tb);
  cudaGetSymbolAddress((void**)&t1ts, g_t1ts);
  cudaGetSymbolAddress((void**)&qkvb, g_qkv);
  cudaGetSymbolAddress((void**)&kb,   g_kb);
  cudaGetSymbolAddress((void**)&ks,   g_ks);
  cudaGetSymbolAddress((void**)&vb,   g_vb);
  cudaGetSymbolAddress((void**)&vs,   g_vs);
  cudaGetSymbolAddress((void**)&avb,  g_av);
  cudaGetSymbolAddress((void**)&t2tb, g_t2tb);
  cudaGetSymbolAddress((void**)&t2ts, g_t2ts);
  cudaGetSymbolAddress((void**)&w1b,  g_w1b);
  cudaGetSymbolAddress((void**)&w1s,  g_w1s);
  cudaGetSymbolAddress((void**)&w2b,  g_w2b);
  cudaGetSymbolAddress((void**)&w2s,  g_w2s);

  const int mm_smem = 2*MMSTG*4;   // 81920 B, double-buffered
  cudaFuncSetAttribute(mm_bf16, cudaFuncAttributeMaxDynamicSharedMemorySize, mm_smem);
  const int at_smem = 49216*4;     // 196864 B
  cudaFuncSetAttribute(attn_k, cudaFuncAttributeMaxDynamicSharedMemorySize, at_smem);

  wsplit<<<(768*128+255)/256, 256>>>(pw1, w1b, w1s, 768*128);
  wsplit<<<(256*128+255)/256, 256>>>(pw2, w2b, w2s, 256*128);
  dw_t<<<dim3(NHW/32, 8, NB), 256>>>(x, dw1, t1tb, t1ts);
  mm_bf16<<<dim3(NHW/128, 768/128, NB), 256, mm_smem>>>(w1b, w1s, t1tb, t1ts, qkvb, 768);
  pool_split<<<1024, 256>>>(qkvb, kb, ks, vb, vs);
  attn_k<<<dim3(NHW/QT, NHEADS, NB), 256, at_smem>>>(qkvb, kb, ks, vb, vs,
                                                     relw, relh, attn, avb);
  dw_t<<<dim3(NHW/32, 8, NB), 256>>>(avb, dw2, t2tb, t2ts);
  mm_bf16<<<dim3(NHW/128, 256/128, NB), 256, mm_smem>>>(w2b, w2s, t2tb, t2ts, out, 256);
}

// round 16
// speedup vs baseline: 1.3793x; 1.3793x over previous
#include <cuda_runtime.h>
#include <cuda_bf16.h>
#include <math.h>
#include <stdint.h>

#define NB 4
#define NC 256
#define NH 128
#define NW 128
#define NHW (NH*NW)
#define NINNER 256
#define NHEADS 4
#define NDH 64
#define NS 16
#define NSS 256
#define QT 64
#define GK 256

// -------- scratch --------
__device__ uint32_t g_t1tb[NB*NHW*128];
__device__ uint32_t g_t1ts[NB*NHW*128];
__device__ float    g_qkv [NB*3*NINNER*NHW];
__device__ uint32_t g_kb  [NB*NHEADS*8192];   // permuted fill-order layout
__device__ uint32_t g_ks  [NB*NHEADS*8192];
__device__ uint32_t g_vb  [NB*NHEADS*64*128];
__device__ uint32_t g_vs  [NB*NHEADS*64*128];
__device__ float    g_av  [NB*NINNER*NHW];
__device__ uint32_t g_t2tb[NB*NHW*128];
__device__ uint32_t g_t2ts[NB*NHW*128];
__device__ uint32_t g_w1b [768*128];
__device__ uint32_t g_w1s [768*128];
__device__ uint32_t g_w2b [256*128];
__device__ uint32_t g_w2s [256*128];

// ---- bf16x3 helpers ----
__device__ __forceinline__ void splitpack(float x0, float x1, uint32_t& b, uint32_t& s) {
  __nv_bfloat162 hb = __floats2bfloat162_rn(x0, x1);
  uint32_t bb = *(uint32_t*)&hb;
  float b0 = __uint_as_float(bb << 16);
  float b1 = __uint_as_float(bb & 0xffff0000u);
  __nv_bfloat162 hs = __floats2bfloat162_rn(x0 - b0, x1 - b1);
  b = bb;
  s = *(uint32_t*)&hs;
}
__device__ __forceinline__ void mma16(float* c, const uint32_t* a, const uint32_t* b) {
  asm volatile("mma.sync.aligned.m16n8k16.row.col.f32.bf16.bf16.f32 "
    "{%0,%1,%2,%3}, {%4,%5,%6,%7}, {%8,%9}, {%0,%1,%2,%3};"
    : "+f"(c[0]), "+f"(c[1]), "+f"(c[2]), "+f"(c[3])
    : "r"(a[0]), "r"(a[1]), "r"(a[2]), "r"(a[3]), "r"(b[0]), "r"(b[1]));
}

// ============== fused depthwise 3x3 (pad 1, smem-tiled) + transpose + bf16x3 split ==============
__global__ void __launch_bounds__(256) dw_t(const float* __restrict__ in,
                                            const float* __restrict__ wt,
                                            uint32_t* __restrict__ outb,
                                            uint32_t* __restrict__ outs) {
  __shared__ float sin_[32][3][36];
  __shared__ float t[32][33];
  int hw0 = blockIdx.x*32, c0 = blockIdx.y*32, b = blockIdx.z;
  int tx = threadIdx.x & 31, ty = threadIdx.x >> 5;
  int y = hw0 >> 7, xb = hw0 & (NW-1);   // all 32 pixels share row y

  // stage 3 input rows (+1 halo each side in x) for 32 channels
  #pragma unroll
  for (int r = 0; r < 4; r++) {
    int cl = ty + r*8;
    const float* ip = in + ((size_t)b*256 + c0 + cl)*NHW;
    #pragma unroll
    for (int dy = 0; dy < 3; dy++) {
      int yy = y + dy - 1;
      bool yok = (unsigned)yy < NH;
      int xx = xb - 1 + tx;
      sin_[cl][dy][tx] = (yok && (unsigned)xx < NW) ? ip[yy*NW + xx] : 0.f;
      if (tx < 2) {
        int x2 = xb + 31 + tx;
        sin_[cl][dy][32+tx] = (yok && (unsigned)x2 < NW) ? ip[yy*NW + x2] : 0.f;
      }
    }
  }
  __syncthreads();

  #pragma unroll
  for (int r = 0; r < 4; r++) {
    int cl = ty + r*8;
    const float* wp = wt + (c0 + cl)*9;
    float s = 0.f;
    #pragma unroll
    for (int dy = 0; dy < 3; dy++)
      #pragma unroll
      for (int dx = 0; dx < 3; dx++)
        s = fmaf(sin_[cl][dy][tx+dx], wp[dy*3+dx], s);
    t[cl][tx] = s;
  }
  __syncthreads();

  #pragma unroll
  for (int e0 = 0; e0 < 2; e0++) {
    int e = e0*256 + threadIdx.x;
    int pp = e & 15, hwl = e >> 4;
    uint32_t pb, ps;
    splitpack(t[2*pp][hwl], t[2*pp+1][hwl], pb, ps);
    size_t o = ((size_t)b*NHW + hw0 + hwl)*128 + (c0 >> 1) + pp;
    outb[o] = pb;
    outs[o] = ps;
  }
}

// ============== weight pre-split ==============
__global__ void wsplit(const float* __restrict__ w, uint32_t* __restrict__ wb,
                       uint32_t* __restrict__ ws_, int n) {
  int e = blockIdx.x*256 + threadIdx.x;
  if (e < n) {
    int m = e >> 7, cp = e & 127;
    splitpack(w[m*256 + 2*cp], w[m*256 + 2*cp + 1], wb[e], ws_[e]);
  }
}

// ======================= bf16x3 mma.sync GEMM (pre-split operands, K-chunk 32 pairs) =======================
#define GP 36
__global__ void __launch_bounds__(256, 2) mm_bf16(const uint32_t* __restrict__ Ab,
                                                  const uint32_t* __restrict__ As,
                                                  const uint32_t* __restrict__ Btb,
                                                  const uint32_t* __restrict__ Bts,
                                                  float* __restrict__ C, int M) {
  extern __shared__ uint32_t sh[];
  uint32_t* sAb = sh;
  uint32_t* sAs = sh + 4608;
  uint32_t* sBb = sh + 9216;
  uint32_t* sBs = sh + 13824;

  const int tid = threadIdx.x;
  const int wid = tid >> 5, lane = tid & 31;
  const int wm = wid >> 2, wn = wid & 3;
  const int g = lane >> 2, tg = lane & 3;
  const int n0 = blockIdx.x * 128;
  const int m0 = blockIdx.y * 128;
  const int bz = blockIdx.z;

  const uint32_t* Ab0 = Ab + (size_t)m0*128;
  const uint32_t* As0 = As + (size_t)m0*128;
  const uint32_t* Bb0 = Btb + ((size_t)bz*NHW + n0)*128;
  const uint32_t* Bs0 = Bts + ((size_t)bz*NHW + n0)*128;

  float acc[4][4][4];
  #pragma unroll
  for (int i=0;i<4;i++)
    #pragma unroll
    for (int j=0;j<4;j++)
      #pragma unroll
      for (int l=0;l<4;l++) acc[i][j][l] = 0.f;

  for (int kcp = 0; kcp < 128; kcp += 32) {
    #pragma unroll
    for (int i = 0; i < 4; i++) {
      int e = i*256 + tid;             // 1024 uint4 slots per array
      int r = e >> 3, c4 = e & 7;
      int so = r*GP + c4*4;
      size_t go = (size_t)r*128 + kcp + c4*4;
      *(uint4*)&sAb[so] = *(const uint4*)&Ab0[go];
      *(uint4*)&sAs[so] = *(const uint4*)&As0[go];
      *(uint4*)&sBb[so] = *(const uint4*)&Bb0[go];
      *(uint4*)&sBs[so] = *(const uint4*)&Bs0[go];
    }
    __syncthreads();
    #pragma unroll
    for (int ks = 0; ks < 4; ks++) {
      int k0 = ks*8;
      uint32_t bb[4][2], bs[4][2];
      #pragma unroll
      for (int nt = 0; nt < 4; nt++) {
        int n = wn*32 + nt*8 + g;
        bb[nt][0] = sBb[n*GP + k0 + tg];
        bb[nt][1] = sBb[n*GP + k0 + tg + 4];
        bs[nt][0] = sBs[n*GP + k0 + tg];
        bs[nt][1] = sBs[n*GP + k0 + tg + 4];
      }
      #pragma unroll
      for (int mt = 0; mt < 4; mt++) {
        int m = wm*64 + mt*16 + g;
        uint32_t ab[4], as_[4];
        ab[0]  = sAb[m*GP + k0 + tg];
        ab[1]  = sAb[(m+8)*GP + k0 + tg];
        ab[2]  = sAb[m*GP + k0 + tg + 4];
        ab[3]  = sAb[(m+8)*GP + k0 + tg + 4];
        as_[0] = sAs[m*GP + k0 + tg];
        as_[1] = sAs[(m+8)*GP + k0 + tg];
        as_[2] = sAs[m*GP + k0 + tg + 4];
        as_[3] = sAs[(m+8)*GP + k0 + tg + 4];
        #pragma unroll
        for (int nt = 0; nt < 4; nt++) {
          mma16(acc[mt][nt], ab,  bb[nt]);
          mma16(acc[mt][nt], ab,  bs[nt]);
          mma16(acc[mt][nt], as_, bb[nt]);
        }
      }
    }
    __syncthreads();
  }

  float* Cb = C + (size_t)bz*M*NHW;
  #pragma unroll
  for (int mt = 0; mt < 4; mt++) {
    int row = m0 + wm*64 + mt*16 + g;
    #pragma unroll
    for (int nt = 0; nt < 4; nt++) {
      int col = n0 + wn*32 + nt*8 + 2*tg;
      *(float2*)(Cb + (size_t)row*NHW + col) =
          make_float2(acc[mt][nt][0], acc[mt][nt][1]);
      *(float2*)(Cb + (size_t)(row+8)*NHW + col) =
          make_float2(acc[mt][nt][2], acc[mt][nt][3]);
    }
  }
}

// ======================= 8x8 max pool + bf16x3 split =======================
__global__ void pool_split(const float* __restrict__ qkv,
                           uint32_t* __restrict__ kb, uint32_t* __restrict__ ks_,
                           uint32_t* __restrict__ vb, uint32_t* __restrict__ vs_) {
  int idx = blockIdx.x*256 + threadIdx.x;   // 0..262143
  int which = idx >> 17;
  int r = idx & 131071;
  int bh = r >> 13;
  int b = bh >> 2, head = bh & 3;
  if (which == 0) {
    int rem = r & 8191;
    int u = rem >> 5, lane = rem & 31;
    int j  = ((u >> 3) << 3) | (lane >> 2);
    int dp = ((u & 7) << 2) | (lane & 3);
    int oh = j >> 4, ow = j & 15;
    const float* p0 = qkv + ((size_t)(b*768 + 256 + 8*dp + head))*NHW + (oh*8)*NW + ow*8;
    const float* p1 = p0 + (size_t)4*NHW;
    float m0 = -1e30f, m1 = -1e30f;
    #pragma unroll
    for (int i = 0; i < 8; i++)
      #pragma unroll
      for (int jj = 0; jj < 8; jj++) {
        m0 = fmaxf(m0, p0[i*NW+jj]);
        m1 = fmaxf(m1, p1[i*NW+jj]);
      }
    splitpack(m0, m1, kb[r], ks_[r]);
  } else {
    int d = (r >> 7) & 63, jp = r & 127;
    int j0 = 2*jp;
    int oh = j0 >> 4, ow = j0 & 15;
    const float* p = qkv + ((size_t)(b*768 + 512 + 4*d + head))*NHW + (oh*8)*NW + ow*8;
    float m0 = -1e30f, m1 = -1e30f;
    #pragma unroll
    for (int i = 0; i < 8; i++)
      #pragma unroll
      for (int jj = 0; jj < 8; jj++) {
        m0 = fmaxf(m0, p[i*NW+jj]);
        m1 = fmaxf(m1, p[i*NW+8+jj]);
      }
    splitpack(m0, m1, vb[r], vs_[r]);
  }
}

// ======================= fused bf16x3 attention, QT=64, fused softmax =======================
#define SSTR 260
#define KPP 36
#define QPP 36
#define RPP 36
#define PPP 132
#define VPP 68
#define LSTR 68
#define OSTR 66

__global__ void __launch_bounds__(256) attn_k(
    const float* __restrict__ qkv,
    const uint32_t* __restrict__ kb, const uint32_t* __restrict__ ks_,
    const uint32_t* __restrict__ vb, const uint32_t* __restrict__ vs_,
    const float* __restrict__ relw, const float* __restrict__ relh,
    float* __restrict__ attn_out, float* __restrict__ av) {
  extern __shared__ float smf[];
  uint32_t* smu = (uint32_t*)smf;
  float*    sS  = smf;                    // 16640
  uint32_t* sKb = smu + 16640;            // 9216
  uint32_t* sKs = smu + 25856;            // 9216
  uint32_t* sQb = smu + 35072;            // 2304
  uint32_t* sQs = smu + 37376;            // 2304
  uint32_t* sRb = smu + 39680;            // 2304
  uint32_t* sRs = smu + 41984;            // 2304
  float*    sL  = smf + 44288;            // 4352
  float*    sM  = smf + 48640;            // 512
  float*    sInv= smf + 49152;            // 64
  uint32_t* sPb = sKb;                    // P overlays K
  uint32_t* sPs = sKs;
  uint32_t* sVb = smu + 35072;            // V halves overlay Q+R
  uint32_t* sVs = smu + 39424;
  float*    sO  = smf;                    // out overlays sS

  const int tid = threadIdx.x;
  const int wid = tid >> 5, lane = tid & 31;
  const int g = lane >> 2, tg = lane & 3;
  const int head = blockIdx.y;
  const int b = blockIdx.z;
  const int i0 = blockIdx.x*QT;
  const int hq = i0 >> 7;
  const int w0 = i0 & (NW-1);
  const int h8 = hq >> 3;

  // ---- load Q, split+pack: unit pattern (g -> qi-in-8, tg -> dp-in-4), bank 4g+tg ----
  #pragma unroll
  for (int it = 0; it < 8; it++) {
    int u = it*8 + wid;               // 0..63
    int qi = (u >> 3)*8 + g;
    int dp = (u & 7)*4 + tg;
    float x0 = qkv[((size_t)(b*768) + 8*dp + head)*NHW + i0 + qi];
    float x1 = qkv[((size_t)(b*768) + 8*dp + 4 + head)*NHW + i0 + qi];
    splitpack(x0, x1, sQb[qi*QPP + dp], sQs[qi*QPP + dp]);
  }
  // ---- rel tables padded to 64 rows: 0..30 relh, 32..62 relw (same unit pattern) ----
  #pragma unroll
  for (int it = 0; it < 8; it++) {
    int u = it*8 + wid;
    int n  = (u >> 3)*8 + g;
    int dp = (u & 7)*4 + tg;
    float x0 = 0.f, x1 = 0.f;
    if (n < 31)                 { x0 = relh[n*64 + 2*dp];      x1 = relh[n*64 + 2*dp + 1]; }
    else if (n >= 32 && n < 63) { x0 = relw[(n-32)*64 + 2*dp]; x1 = relw[(n-32)*64 + 2*dp + 1]; }
    splitpack(x0, x1, sRb[n*RPP + dp], sRs[n*RPP + dp]);
  }
  // ---- load pre-split K from permuted gmem layout (coalesced + conflict-free) ----
  {
    const uint32_t* kbp = kb  + (size_t)(b*NHEADS + head)*8192;
    const uint32_t* ksp = ks_ + (size_t)(b*NHEADS + head)*8192;
    #pragma unroll 8
    for (int it = 0; it < 32; it++) {
      int u = it*8 + wid;             // 0..255
      int j  = (u >> 3)*8 + g;
      int dp = (u & 7)*4 + tg;
      sKb[j*KPP + dp] = kbp[u*32 + lane];
      sKs[j*KPP + dp] = ksp[u*32 + lane];
    }
  }
  __syncthreads();

  // ================= QK scores (acc stays in regs) =================
  const int n0w = wid*32;
  float acc[4][4][4];
  #pragma unroll
  for (int i=0;i<4;i++)
    #pragma unroll
    for (int j=0;j<4;j++)
      #pragma unroll
      for (int l=0;l<4;l++) acc[i][j][l]=0.f;
  #pragma unroll
  for (int ks = 0; ks < 4; ks++) {
    int k0 = ks*8;
    uint32_t bb[4][2], bs[4][2];
    #pragma unroll
    for (int nt = 0; nt < 4; nt++) {
      int j = n0w + nt*8 + g;
      bb[nt][0] = sKb[j*KPP + k0 + tg];
      bb[nt][1] = sKb[j*KPP + k0 + tg + 4];
      bs[nt][0] = sKs[j*KPP + k0 + tg];
      bs[nt][1] = sKs[j*KPP + k0 + tg + 4];
    }
    #pragma unroll
    for (int mt = 0; mt < 4; mt++) {
      int q = mt*16 + g;
      uint32_t ab[4], as_[4];
      ab[0]  = sQb[q*QPP + k0 + tg];
      ab[1]  = sQb[(q+8)*QPP + k0 + tg];
      ab[2]  = sQb[q*QPP + k0 + tg + 4];
      ab[3]  = sQb[(q+8)*QPP + k0 + tg + 4];
      as_[0] = sQs[q*QPP + k0 + tg];
      as_[1] = sQs[(q+8)*QPP + k0 + tg];
      as_[2] = sQs[q*QPP + k0 + tg + 4];
      as_[3] = sQs[(q+8)*QPP + k0 + tg + 4];
      #pragma unroll
      for (int nt = 0; nt < 4; nt++) {
        mma16(acc[mt][nt], ab,  bb[nt]);
        mma16(acc[mt][nt], ab,  bs[nt]);
        mma16(acc[mt][nt], as_, bb[nt]);
      }
    }
  }
  // ================= bias logits (64 x 64, warp = 8 cols) =================
  {
    float acc2[4][4];
    #pragma unroll
    for (int i=0;i<4;i++)
      #pragma unroll
      for (int l=0;l<4;l++) acc2[i][l]=0.f;
    #pragma unroll
    for (int ks = 0; ks < 4; ks++) {
      int k0 = ks*8;
      int n = wid*8 + g;
      uint32_t bb[2], bs[2];
      bb[0] = sRb[n*RPP + k0 + tg];
      bb[1] = sRb[n*RPP + k0 + tg + 4];
      bs[0] = sRs[n*RPP + k0 + tg];
      bs[1] = sRs[n*RPP + k0 + tg + 4];
      #pragma unroll
      for (int mt = 0; mt < 4; mt++) {
        int q = mt*16 + g;
        uint32_t ab[4], as_[4];
        ab[0]  = sQb[q*QPP + k0 + tg];
        ab[1]  = sQb[(q+8)*QPP + k0 + tg];
        ab[2]  = sQb[q*QPP + k0 + tg + 4];
        ab[3]  = sQb[(q+8)*QPP + k0 + tg + 4];
        as_[0] = sQs[q*QPP + k0 + tg];
        as_[1] = sQs[(q+8)*QPP + k0 + tg];
        as_[2] = sQs[q*QPP + k0 + tg + 4];
        as_[3] = sQs[(q+8)*QPP + k0 + tg + 4];
        mma16(acc2[mt], ab,  bb);
        mma16(acc2[mt], ab,  bs);
        mma16(acc2[mt], as_, bb);
      }
    }
    #pragma unroll
    for (int mt = 0; mt < 4; mt++) {
      int q = mt*16 + g;
      int col = wid*8 + 2*tg;
      *(float2*)&sL[q*LSTR + col]     = make_float2(acc2[mt][0], acc2[mt][1]);
      *(float2*)&sL[(q+8)*LSTR + col] = make_float2(acc2[mt][2], acc2[mt][3]);
    }
  }
  __syncthreads();

  // ======= QK epilogue: add bias, scale, store scores, row-max partials =======
  #pragma unroll
  for (int mt = 0; mt < 4; mt++) {
    #pragma unroll
    for (int rr = 0; rr < 2; rr++) {
      int qq = mt*16 + rr*8 + g;
      const float* lrow = sL + qq*LSTR;
      const int w8 = (w0 + qq) >> 3;
      float mxv = -1e30f;
      #pragma unroll
      for (int nt = 0; nt < 4; nt++) {
        int col = n0w + nt*8 + 2*tg;
        float lh  = lrow[(col >> 4) - h8 + 15];
        float lw0 = lrow[32 + (col & 15) - w8 + 15];
        float lw1 = lrow[32 + ((col+1) & 15) - w8 + 15];
        float s0 = (acc[mt][nt][rr*2+0] + lh + lw0) * 0.125f;
        float s1 = (acc[mt][nt][rr*2+1] + lh + lw1) * 0.125f;
        *(float2*)&sS[qq*SSTR + col] = make_float2(s0, s1);
        mxv = fmaxf(mxv, fmaxf(s0, s1));
      }
      mxv = fmaxf(mxv, __shfl_xor_sync(0xffffffffu, mxv, 1));
      mxv = fmaxf(mxv, __shfl_xor_sync(0xffffffffu, mxv, 2));
      if (tg == 0) sM[qq*8 + wid] = mxv;
    }
  }
  __syncthreads();

  // ======= exp + sum in one pass (4 threads/query); V half 0 load =======
  {
    const int q = tid >> 2, l4 = tid & 3;
    float* srow = sS + q*SSTR;
    float mx = sM[q*8];
    #pragma unroll
    for (int w = 1; w < 8; w++) mx = fmaxf(mx, sM[q*8 + w]);
    float sum = 0.f;
    #pragma unroll
    for (int i = 0; i < 64; i++) {
      int j = i*4 + l4;
      float e2 = __expf(srow[j] - mx);
      srow[j] = e2;
      sum += e2;
    }
    sum += __shfl_xor_sync(0xffffffffu, sum, 1);
    sum += __shfl_xor_sync(0xffffffffu, sum, 2);
    if (l4 == 0) sInv[q] = 1.f / sum;
  }
  {
    const uint32_t* vbp = vb  + ((size_t)(b*NHEADS + head)*64)*128;
    const uint32_t* vsp = vs_ + ((size_t)(b*NHEADS + head)*64)*128;
    #pragma unroll
    for (int it = 0; it < 16; it++) {
      int e = it*256 + tid;
      int d = e >> 6, jp = e & 63;
      sVb[d*VPP + jp] = vbp[d*128 + jp];
      sVs[d*VPP + jp] = vsp[d*128 + jp];
    }
  }
  __syncthreads();

  // ======= attn write (normalized) + P split into dead K region =======
  float* aout = attn_out + ((size_t)(b*NHEADS + head)*NHW + i0)*NSS;
  #pragma unroll 4
  for (int it = 0; it < 32; it++) {
    int e = it*256 + tid;
    int qi = e >> 7, jp = e & 127;
    float inv = sInv[qi];
    float2 p2 = *(const float2*)&sS[qi*SSTR + 2*jp];
    p2.x *= inv; p2.y *= inv;
    *(float2*)&aout[(size_t)qi*NSS + 2*jp] = p2;
    splitpack(p2.x, p2.y, sPb[qi*PPP + jp], sPs[qi*PPP + jp]);
  }
  __syncthreads();

  // ================= AV (two j-halves) =================
  {
    const int wm = wid >> 2, wn = wid & 3;   // 2 x 4
    float acc3[2][2][4];
    #pragma unroll
    for (int i=0;i<2;i++)
      #pragma unroll
      for (int j=0;j<2;j++)
        #pragma unroll
        for (int l=0;l<4;l++) acc3[i][j][l]=0.f;

    #pragma unroll 1
    for (int half = 0; half < 2; half++) {
      if (half == 1) {
        __syncthreads();
        const uint32_t* vbp = vb  + ((size_t)(b*NHEADS + head)*64)*128 + 64;
        const uint32_t* vsp = vs_ + ((size_t)(b*NHEADS + head)*64)*128 + 64;
        #pragma unroll
        for (int it = 0; it < 16; it++) {
          int e = it*256 + tid;
          int d = e >> 6, jp = e & 63;
          sVb[d*VPP + jp] = vbp[d*128 + jp];
          sVs[d*VPP + jp] = vsp[d*128 + jp];
        }
        __syncthreads();
      }
      const int p0 = half*64;
      #pragma unroll 4
      for (int ks = 0; ks < 8; ks++) {
        int k0 = ks*8;
        uint32_t ab[2][4], as_[2][4];
        #pragma unroll
        for (int mt = 0; mt < 2; mt++) {
          int q = wm*32 + mt*16 + g;
          ab[mt][0]  = sPb[q*PPP + p0 + k0 + tg];
          ab[mt][1]  = sPb[(q+8)*PPP + p0 + k0 + tg];
          ab[mt][2]  = sPb[q*PPP + p0 + k0 + tg + 4];
          ab[mt][3]  = sPb[(q+8)*PPP + p0 + k0 + tg + 4];
          as_[mt][0] = sPs[q*PPP + p0 + k0 + tg];
          as_[mt][1] = sPs[(q+8)*PPP + p0 + k0 + tg];
          as_[mt][2] = sPs[q*PPP + p0 + k0 + tg + 4];
          as_[mt][3] = sPs[(q+8)*PPP + p0 + k0 + tg + 4];
        }
        uint32_t bb[2][2], bs[2][2];
        #pragma unroll
        for (int nt = 0; nt < 2; nt++) {
          int d = wn*16 + nt*8 + g;
          bb[nt][0] = sVb[d*VPP + k0 + tg];
          bb[nt][1] = sVb[d*VPP + k0 + tg + 4];
          bs[nt][0] = sVs[d*VPP + k0 + tg];
          bs[nt][1] = sVs[d*VPP + k0 + tg + 4];
        }
        #pragma unroll
        for (int mt = 0; mt < 2; mt++)
          #pragma unroll
          for (int nt = 0; nt < 2; nt++) {
            mma16(acc3[mt][nt], ab[mt],  bb[nt]);
            mma16(acc3[mt][nt], ab[mt],  bs[nt]);
            mma16(acc3[mt][nt], as_[mt], bb[nt]);
          }
      }
    }
    #pragma unroll
    for (int mt = 0; mt < 2; mt++) {
      int q = wm*32 + mt*16 + g;
      #pragma unroll
      for (int nt = 0; nt < 2; nt++) {
        int col = wn*16 + nt*8 + 2*tg;
        *(float2*)&sO[q*OSTR + col]     = make_float2(acc3[mt][nt][0], acc3[mt][nt][1]);
        *(float2*)&sO[(q+8)*OSTR + col] = make_float2(acc3[mt][nt][2], acc3[mt][nt][3]);
      }
    }
  }
  __syncthreads();
  #pragma unroll
  for (int l = 0; l < 16; l++) {
    int e = l*256 + tid;
    int d = e >> 6, qi = e & 63;
    av[((size_t)(b*NINNER) + d*NHEADS + head)*NHW + i0 + qi] = sO[qi*OSTR + d];
  }
}

// ======================= launch =======================
extern "C" void kernel_launch(void* const* d_in, const int* in_sizes, int n_in,
                              void* d_out, int out_size) {
  const float* x    = (const float*)d_in[0];
  const float* dw1  = (const float*)d_in[1];
  const float* pw1  = (const float*)d_in[2];
  const float* relw = (const float*)d_in[3];
  const float* relh = (const float*)d_in[4];
  const float* dw2  = (const float*)d_in[5];
  const float* pw2  = (const float*)d_in[6];

  float* out  = (float*)d_out;
  float* attn = out + (size_t)NB*NINNER*NHW;

  uint32_t *t1tb, *t1ts, *t2tb, *t2ts, *kb, *ks, *vb, *vs;
  uint32_t *w1b, *w1s, *w2b, *w2s;
  float *qkvb, *avb;
  cudaGetSymbolAddress((void**)&t1tb, g_t1tb);
  cudaGetSymbolAddress((void**)&t1ts, g_t1ts);
  cudaGetSymbolAddress((void**)&qkvb, g_qkv);
  cudaGetSymbolAddress((void**)&kb,   g_kb);
  cudaGetSymbolAddress((void**)&ks,   g_ks);
  cudaGetSymbolAddress((void**)&vb,   g_vb);
  cudaGetSymbolAddress((void**)&vs,   g_vs);
  cudaGetSymbolAddress((void**)&avb,  g_av);
  cudaGetSymbolAddress((void**)&t2tb, g_t2tb);
  cudaGetSymbolAddress((void**)&t2ts, g_t2ts);
  cudaGetSymbolAddress((void**)&w1b,  g_w1b);
  cudaGetSymbolAddress((void**)&w1s,  g_w1s);
  cudaGetSymbolAddress((void**)&w2b,  g_w2b);
  cudaGetSymbolAddress((void**)&w2s,  g_w2s);

  const int mm_smem = 4*128*GP*4;  // 73728 B, 2 CTAs/SM
  cudaFuncSetAttribute(mm_bf16, cudaFuncAttributeMaxDynamicSharedMemorySize, mm_smem);
  const int at_smem = 49216*4;     // 196864 B
  cudaFuncSetAttribute(attn_k, cudaFuncAttributeMaxDynamicSharedMemorySize, at_smem);

  wsplit<<<(768*128+255)/256, 256>>>(pw1, w1b, w1s, 768*128);
  wsplit<<<(256*128+255)/256, 256>>>(pw2, w2b, w2s, 256*128);
  dw_t<<<dim3(NHW/32, 8, NB), 256>>>(x, dw1, t1tb, t1ts);
  mm_bf16<<<dim3(NHW/128, 768/128, NB), 256, mm_smem>>>(w1b, w1s, t1tb, t1ts, qkvb, 768);
  pool_split<<<1024, 256>>>(qkvb, kb, ks, vb, vs);
  attn_k<<<dim3(NHW/QT, NHEADS, NB), 256, at_smem>>>(qkvb, kb, ks, vb, vs,
                                                     relw, relh, attn, avb);
  dw_t<<<dim3(NHW/32, 8, NB), 256>>>(avb, dw2, t2tb, t2ts);
  mm_bf16<<<dim3(NHW/128, 256/128, NB), 256, mm_smem>>>(w2b, w2s, t2tb, t2ts, out, 256);
}

// round 17
// speedup vs baseline: 1.5171x; 1.0999x over previous
#include <cuda_runtime.h>
#include <cuda_bf16.h>
#include <math.h>
#include <stdint.h>

#define NB 4
#define NC 256
#define NH 128
#define NW 128
#define NHW (NH*NW)
#define NINNER 256
#define NHEADS 4
#define NDH 64
#define NS 16
#define NSS 256
#define QT 64
#define GK 256

// -------- scratch --------
__device__ uint32_t g_t1tb[NB*NHW*128];
__device__ uint32_t g_t1ts[NB*NHW*128];
__device__ float    g_qkv [NB*3*NINNER*NHW];
__device__ uint32_t g_kb  [NB*NHEADS*8192];   // permuted fill-order layout
__device__ uint32_t g_ks  [NB*NHEADS*8192];
__device__ uint32_t g_vb  [NB*NHEADS*64*128];
__device__ uint32_t g_vs  [NB*NHEADS*64*128];
__device__ float    g_av  [NB*NINNER*NHW];
__device__ uint32_t g_t2tb[NB*NHW*128];
__device__ uint32_t g_t2ts[NB*NHW*128];
__device__ uint32_t g_w1b [768*128];
__device__ uint32_t g_w1s [768*128];
__device__ uint32_t g_w2b [256*128];
__device__ uint32_t g_w2s [256*128];

// ---- bf16x3 helpers ----
__device__ __forceinline__ void splitpack(float x0, float x1, uint32_t& b, uint32_t& s) {
  __nv_bfloat162 hb = __floats2bfloat162_rn(x0, x1);
  uint32_t bb = *(uint32_t*)&hb;
  float b0 = __uint_as_float(bb << 16);
  float b1 = __uint_as_float(bb & 0xffff0000u);
  __nv_bfloat162 hs = __floats2bfloat162_rn(x0 - b0, x1 - b1);
  b = bb;
  s = *(uint32_t*)&hs;
}
__device__ __forceinline__ void mma16(float* c, const uint32_t* a, const uint32_t* b) {
  asm volatile("mma.sync.aligned.m16n8k16.row.col.f32.bf16.bf16.f32 "
    "{%0,%1,%2,%3}, {%4,%5,%6,%7}, {%8,%9}, {%0,%1,%2,%3};"
    : "+f"(c[0]), "+f"(c[1]), "+f"(c[2]), "+f"(c[3])
    : "r"(a[0]), "r"(a[1]), "r"(a[2]), "r"(a[3]), "r"(b[0]), "r"(b[1]));
}

// ============== fused depthwise 3x3 (pad 1) + transpose + bf16x3 split ==============
__global__ void __launch_bounds__(256) dw_t(const float* __restrict__ in,
                                            const float* __restrict__ wt,
                                            uint32_t* __restrict__ outb,
                                            uint32_t* __restrict__ outs) {
  __shared__ float t[32][33];
  int hw0 = blockIdx.x*32, c0 = blockIdx.y*32, b = blockIdx.z;
  int tx = threadIdx.x & 31, ty = threadIdx.x >> 5;
  int x = (hw0 + tx) & (NW-1), y = (hw0 + tx) >> 7;
  #pragma unroll
  for (int r = 0; r < 4; r++) {
    int c = c0 + ty + r*8;
    const float* wp = wt + c*9;
    const float* ip = in + ((size_t)b*256 + c)*NHW;
    float s = 0.f;
    #pragma unroll
    for (int dy = -1; dy <= 1; dy++) {
      int yy = y + dy;
      if ((unsigned)yy >= NH) continue;
      #pragma unroll
      for (int dx = -1; dx <= 1; dx++) {
        int xx = x + dx;
        if ((unsigned)xx >= NW) continue;
        s = fmaf(ip[yy*NW+xx], wp[(dy+1)*3 + dx+1], s);
      }
    }
    t[ty + r*8][tx] = s;
  }
  __syncthreads();
  #pragma unroll
  for (int e0 = 0; e0 < 2; e0++) {
    int e = e0*256 + threadIdx.x;
    int pp = e & 15, hwl = e >> 4;
    uint32_t pb, ps;
    splitpack(t[2*pp][hwl], t[2*pp+1][hwl], pb, ps);
    size_t o = ((size_t)b*NHW + hw0 + hwl)*128 + (c0 >> 1) + pp;
    outb[o] = pb;
    outs[o] = ps;
  }
}

// ============== weight pre-split ==============
__global__ void wsplit(const float* __restrict__ w, uint32_t* __restrict__ wb,
                       uint32_t* __restrict__ ws_, int n) {
  int e = blockIdx.x*256 + threadIdx.x;
  if (e < n) {
    int m = e >> 7, cp = e & 127;
    splitpack(w[m*256 + 2*cp], w[m*256 + 2*cp + 1], wb[e], ws_[e]);
  }
}

// ======================= bf16x3 mma.sync GEMM (pre-split operands, K-chunk 32 pairs) =======================
#define GP 36
__global__ void __launch_bounds__(256, 2) mm_bf16(const uint32_t* __restrict__ Ab,
                                                  const uint32_t* __restrict__ As,
                                                  const uint32_t* __restrict__ Btb,
                                                  const uint32_t* __restrict__ Bts,
                                                  float* __restrict__ C, int M) {
  extern __shared__ uint32_t sh[];
  uint32_t* sAb = sh;
  uint32_t* sAs = sh + 4608;
  uint32_t* sBb = sh + 9216;
  uint32_t* sBs = sh + 13824;

  const int tid = threadIdx.x;
  const int wid = tid >> 5, lane = tid & 31;
  const int wm = wid >> 2, wn = wid & 3;
  const int g = lane >> 2, tg = lane & 3;
  const int n0 = blockIdx.x * 128;
  const int m0 = blockIdx.y * 128;
  const int bz = blockIdx.z;

  const uint32_t* Ab0 = Ab + (size_t)m0*128;
  const uint32_t* As0 = As + (size_t)m0*128;
  const uint32_t* Bb0 = Btb + ((size_t)bz*NHW + n0)*128;
  const uint32_t* Bs0 = Bts + ((size_t)bz*NHW + n0)*128;

  float acc[4][4][4];
  #pragma unroll
  for (int i=0;i<4;i++)
    #pragma unroll
    for (int j=0;j<4;j++)
      #pragma unroll
      for (int l=0;l<4;l++) acc[i][j][l] = 0.f;

  for (int kcp = 0; kcp < 128; kcp += 32) {
    #pragma unroll
    for (int i = 0; i < 4; i++) {
      int e = i*256 + tid;             // 1024 uint4 slots per array
      int r = e >> 3, c4 = e & 7;
      int so = r*GP + c4*4;
      size_t go = (size_t)r*128 + kcp + c4*4;
      *(uint4*)&sAb[so] = *(const uint4*)&Ab0[go];
      *(uint4*)&sAs[so] = *(const uint4*)&As0[go];
      *(uint4*)&sBb[so] = *(const uint4*)&Bb0[go];
      *(uint4*)&sBs[so] = *(const uint4*)&Bs0[go];
    }
    __syncthreads();
    #pragma unroll
    for (int ks = 0; ks < 4; ks++) {
      int k0 = ks*8;
      uint32_t bb[4][2], bs[4][2];
      #pragma unroll
      for (int nt = 0; nt < 4; nt++) {
        int n = wn*32 + nt*8 + g;
        bb[nt][0] = sBb[n*GP + k0 + tg];
        bb[nt][1] = sBb[n*GP + k0 + tg + 4];
        bs[nt][0] = sBs[n*GP + k0 + tg];
        bs[nt][1] = sBs[n*GP + k0 + tg + 4];
      }
      #pragma unroll
      for (int mt = 0; mt < 4; mt++) {
        int m = wm*64 + mt*16 + g;
        uint32_t ab[4], as_[4];
        ab[0]  = sAb[m*GP + k0 + tg];
        ab[1]  = sAb[(m+8)*GP + k0 + tg];
        ab[2]  = sAb[m*GP + k0 + tg + 4];
        ab[3]  = sAb[(m+8)*GP + k0 + tg + 4];
        as_[0] = sAs[m*GP + k0 + tg];
        as_[1] = sAs[(m+8)*GP + k0 + tg];
        as_[2] = sAs[m*GP + k0 + tg + 4];
        as_[3] = sAs[(m+8)*GP + k0 + tg + 4];
        #pragma unroll
        for (int nt = 0; nt < 4; nt++) {
          mma16(acc[mt][nt], ab,  bb[nt]);
          mma16(acc[mt][nt], ab,  bs[nt]);
          mma16(acc[mt][nt], as_, bb[nt]);
        }
      }
    }
    __syncthreads();
  }

  float* Cb = C + (size_t)bz*M*NHW;
  #pragma unroll
  for (int mt = 0; mt < 4; mt++) {
    int row = m0 + wm*64 + mt*16 + g;
    #pragma unroll
    for (int nt = 0; nt < 4; nt++) {
      int col = n0 + wn*32 + nt*8 + 2*tg;
      *(float2*)(Cb + (size_t)row*NHW + col) =
          make_float2(acc[mt][nt][0], acc[mt][nt][1]);
      *(float2*)(Cb + (size_t)(row+8)*NHW + col) =
          make_float2(acc[mt][nt][2], acc[mt][nt][3]);
    }
  }
}

// ======================= 8x8 max pool + bf16x3 split =======================
__global__ void pool_split(const float* __restrict__ qkv,
                           uint32_t* __restrict__ kb, uint32_t* __restrict__ ks_,
                           uint32_t* __restrict__ vb, uint32_t* __restrict__ vs_) {
  int idx = blockIdx.x*256 + threadIdx.x;   // 0..262143
  int which = idx >> 17;
  int r = idx & 131071;
  int bh = r >> 13;
  int b = bh >> 2, head = bh & 3;
  if (which == 0) {
    int rem = r & 8191;
    int u = rem >> 5, lane = rem & 31;
    int j  = ((u >> 3) << 3) | (lane >> 2);
    int dp = ((u & 7) << 2) | (lane & 3);
    int oh = j >> 4, ow = j & 15;
    const float* p0 = qkv + ((size_t)(b*768 + 256 + 8*dp + head))*NHW + (oh*8)*NW + ow*8;
    const float* p1 = p0 + (size_t)4*NHW;
    float m0 = -1e30f, m1 = -1e30f;
    #pragma unroll
    for (int i = 0; i < 8; i++)
      #pragma unroll
      for (int jj = 0; jj < 8; jj++) {
        m0 = fmaxf(m0, p0[i*NW+jj]);
        m1 = fmaxf(m1, p1[i*NW+jj]);
      }
    splitpack(m0, m1, kb[r], ks_[r]);
  } else {
    int d = (r >> 7) & 63, jp = r & 127;
    int j0 = 2*jp;
    int oh = j0 >> 4, ow = j0 & 15;
    const float* p = qkv + ((size_t)(b*768 + 512 + 4*d + head))*NHW + (oh*8)*NW + ow*8;
    float m0 = -1e30f, m1 = -1e30f;
    #pragma unroll
    for (int i = 0; i < 8; i++)
      #pragma unroll
      for (int jj = 0; jj < 8; jj++) {
        m0 = fmaxf(m0, p[i*NW+jj]);
        m1 = fmaxf(m1, p[i*NW+8+jj]);
      }
    splitpack(m0, m1, vb[r], vs_[r]);
  }
}

// ======================= fused bf16x3 attention, QT=64, fused softmax =======================
#define SSTR 260
#define KPP 36
#define QPP 36
#define RPP 36
#define PPP 132
#define VPP 68
#define LSTR 68
#define OSTR 66

__global__ void __launch_bounds__(256) attn_k(
    const float* __restrict__ qkv,
    const uint32_t* __restrict__ kb, const uint32_t* __restrict__ ks_,
    const uint32_t* __restrict__ vb, const uint32_t* __restrict__ vs_,
    const float* __restrict__ relw, const float* __restrict__ relh,
    float* __restrict__ attn_out, float* __restrict__ av) {
  extern __shared__ float smf[];
  uint32_t* smu = (uint32_t*)smf;
  float*    sS  = smf;                    // 16640
  uint32_t* sKb = smu + 16640;            // 9216
  uint32_t* sKs = smu + 25856;            // 9216
  uint32_t* sQb = smu + 35072;            // 2304
  uint32_t* sQs = smu + 37376;            // 2304
  uint32_t* sRb = smu + 39680;            // 2304
  uint32_t* sRs = smu + 41984;            // 2304
  float*    sL  = smf + 44288;            // 4352
  float*    sM  = smf + 48640;            // 512
  float*    sInv= smf + 49152;            // 64
  uint32_t* sPb = sKb;                    // P overlays K
  uint32_t* sPs = sKs;
  uint32_t* sVb = smu + 35072;            // V halves overlay Q+R
  uint32_t* sVs = smu + 39424;
  float*    sO  = smf;                    // out overlays sS

  const int tid = threadIdx.x;
  const int wid = tid >> 5, lane = tid & 31;
  const int g = lane >> 2, tg = lane & 3;
  const int head = blockIdx.y;
  const int b = blockIdx.z;
  const int i0 = blockIdx.x*QT;
  const int hq = i0 >> 7;
  const int w0 = i0 & (NW-1);
  const int h8 = hq >> 3;

  // ---- load Q, split+pack: unit pattern (g -> qi-in-8, tg -> dp-in-4), bank 4g+tg ----
  #pragma unroll
  for (int it = 0; it < 8; it++) {
    int u = it*8 + wid;               // 0..63
    int qi = (u >> 3)*8 + g;
    int dp = (u & 7)*4 + tg;
    float x0 = qkv[((size_t)(b*768) + 8*dp + head)*NHW + i0 + qi];
    float x1 = qkv[((size_t)(b*768) + 8*dp + 4 + head)*NHW + i0 + qi];
    splitpack(x0, x1, sQb[qi*QPP + dp], sQs[qi*QPP + dp]);
  }
  // ---- rel tables padded to 64 rows: 0..30 relh, 32..62 relw (same unit pattern) ----
  #pragma unroll
  for (int it = 0; it < 8; it++) {
    int u = it*8 + wid;
    int n  = (u >> 3)*8 + g;
    int dp = (u & 7)*4 + tg;
    float x0 = 0.f, x1 = 0.f;
    if (n < 31)                 { x0 = relh[n*64 + 2*dp];      x1 = relh[n*64 + 2*dp + 1]; }
    else if (n >= 32 && n < 63) { x0 = relw[(n-32)*64 + 2*dp]; x1 = relw[(n-32)*64 + 2*dp + 1]; }
    splitpack(x0, x1, sRb[n*RPP + dp], sRs[n*RPP + dp]);
  }
  // ---- load pre-split K from permuted gmem layout (coalesced + conflict-free) ----
  {
    const uint32_t* kbp = kb  + (size_t)(b*NHEADS + head)*8192;
    const uint32_t* ksp = ks_ + (size_t)(b*NHEADS + head)*8192;
    #pragma unroll 8
    for (int it = 0; it < 32; it++) {
      int u = it*8 + wid;             // 0..255
      int j  = (u >> 3)*8 + g;
      int dp = (u & 7)*4 + tg;
      sKb[j*KPP + dp] = kbp[u*32 + lane];
      sKs[j*KPP + dp] = ksp[u*32 + lane];
    }
  }
  __syncthreads();

  // ================= QK scores (acc stays in regs) =================
  const int n0w = wid*32;
  float acc[4][4][4];
  #pragma unroll
  for (int i=0;i<4;i++)
    #pragma unroll
    for (int j=0;j<4;j++)
      #pragma unroll
      for (int l=0;l<4;l++) acc[i][j][l]=0.f;
  #pragma unroll
  for (int ks = 0; ks < 4; ks++) {
    int k0 = ks*8;
    uint32_t bb[4][2], bs[4][2];
    #pragma unroll
    for (int nt = 0; nt < 4; nt++) {
      int j = n0w + nt*8 + g;
      bb[nt][0] = sKb[j*KPP + k0 + tg];
      bb[nt][1] = sKb[j*KPP + k0 + tg + 4];
      bs[nt][0] = sKs[j*KPP + k0 + tg];
      bs[nt][1] = sKs[j*KPP + k0 + tg + 4];
    }
    #pragma unroll
    for (int mt = 0; mt < 4; mt++) {
      int q = mt*16 + g;
      uint32_t ab[4], as_[4];
      ab[0]  = sQb[q*QPP + k0 + tg];
      ab[1]  = sQb[(q+8)*QPP + k0 + tg];
      ab[2]  = sQb[q*QPP + k0 + tg + 4];
      ab[3]  = sQb[(q+8)*QPP + k0 + tg + 4];
      as_[0] = sQs[q*QPP + k0 + tg];
      as_[1] = sQs[(q+8)*QPP + k0 + tg];
      as_[2] = sQs[q*QPP + k0 + tg + 4];
      as_[3] = sQs[(q+8)*QPP + k0 + tg + 4];
      #pragma unroll
      for (int nt = 0; nt < 4; nt++) {
        mma16(acc[mt][nt], ab,  bb[nt]);
        mma16(acc[mt][nt], ab,  bs[nt]);
        mma16(acc[mt][nt], as_, bb[nt]);
      }
    }
  }
  // ================= bias logits (64 x 64, warp = 8 cols) =================
  {
    float acc2[4][4];
    #pragma unroll
    for (int i=0;i<4;i++)
      #pragma unroll
      for (int l=0;l<4;l++) acc2[i][l]=0.f;
    #pragma unroll
    for (int ks = 0; ks < 4; ks++) {
      int k0 = ks*8;
      int n = wid*8 + g;
      uint32_t bb[2], bs[2];
      bb[0] = sRb[n*RPP + k0 + tg];
      bb[1] = sRb[n*RPP + k0 + tg + 4];
      bs[0] = sRs[n*RPP + k0 + tg];
      bs[1] = sRs[n*RPP + k0 + tg + 4];
      #pragma unroll
      for (int mt = 0; mt < 4; mt++) {
        int q = mt*16 + g;
        uint32_t ab[4], as_[4];
        ab[0]  = sQb[q*QPP + k0 + tg];
        ab[1]  = sQb[(q+8)*QPP + k0 + tg];
        ab[2]  = sQb[q*QPP + k0 + tg + 4];
        ab[3]  = sQb[(q+8)*QPP + k0 + tg + 4];
        as_[0] = sQs[q*QPP + k0 + tg];
        as_[1] = sQs[(q+8)*QPP + k0 + tg];
        as_[2] = sQs[q*QPP + k0 + tg + 4];
        as_[3] = sQs[(q+8)*QPP + k0 + tg + 4];
        mma16(acc2[mt], ab,  bb);
        mma16(acc2[mt], ab,  bs);
        mma16(acc2[mt], as_, bb);
      }
    }
    #pragma unroll
    for (int mt = 0; mt < 4; mt++) {
      int q = mt*16 + g;
      int col = wid*8 + 2*tg;
      *(float2*)&sL[q*LSTR + col]     = make_float2(acc2[mt][0], acc2[mt][1]);
      *(float2*)&sL[(q+8)*LSTR + col] = make_float2(acc2[mt][2], acc2[mt][3]);
    }
  }
  __syncthreads();

  // ======= QK epilogue: add bias, scale, store scores, row-max partials =======
  #pragma unroll
  for (int mt = 0; mt < 4; mt++) {
    #pragma unroll
    for (int rr = 0; rr < 2; rr++) {
      int qq = mt*16 + rr*8 + g;
      const float* lrow = sL + qq*LSTR;
      const int w8 = (w0 + qq) >> 3;
      float mxv = -1e30f;
      #pragma unroll
      for (int nt = 0; nt < 4; nt++) {
        int col = n0w + nt*8 + 2*tg;
        float lh  = lrow[(col >> 4) - h8 + 15];
        float lw0 = lrow[32 + (col & 15) - w8 + 15];
        float lw1 = lrow[32 + ((col+1) & 15) - w8 + 15];
        float s0 = (acc[mt][nt][rr*2+0] + lh + lw0) * 0.125f;
        float s1 = (acc[mt][nt][rr*2+1] + lh + lw1) * 0.125f;
        *(float2*)&sS[qq*SSTR + col] = make_float2(s0, s1);
        mxv = fmaxf(mxv, fmaxf(s0, s1));
      }
      mxv = fmaxf(mxv, __shfl_xor_sync(0xffffffffu, mxv, 1));
      mxv = fmaxf(mxv, __shfl_xor_sync(0xffffffffu, mxv, 2));
      if (tg == 0) sM[qq*8 + wid] = mxv;
    }
  }
  __syncthreads();

  // ======= exp + sum in one pass (4 threads/query); V half 0 load =======
  {
    const int q = tid >> 2, l4 = tid & 3;
    float* srow = sS + q*SSTR;
    float mx = sM[q*8];
    #pragma unroll
    for (int w = 1; w < 8; w++) mx = fmaxf(mx, sM[q*8 + w]);
    float sum = 0.f;
    #pragma unroll
    for (int i = 0; i < 64; i++) {
      int j = i*4 + l4;
      float e2 = __expf(srow[j] - mx);
      srow[j] = e2;
      sum += e2;
    }
    sum += __shfl_xor_sync(0xffffffffu, sum, 1);
    sum += __shfl_xor_sync(0xffffffffu, sum, 2);
    if (l4 == 0) sInv[q] = 1.f / sum;
  }
  {
    const uint32_t* vbp = vb  + ((size_t)(b*NHEADS + head)*64)*128;
    const uint32_t* vsp = vs_ + ((size_t)(b*NHEADS + head)*64)*128;
    #pragma unroll
    for (int it = 0; it < 16; it++) {
      int e = it*256 + tid;
      int d = e >> 6, jp = e & 63;
      sVb[d*VPP + jp] = vbp[d*128 + jp];
      sVs[d*VPP + jp] = vsp[d*128 + jp];
    }
  }
  __syncthreads();

  // ======= attn write (normalized) + P split into dead K region =======
  float* aout = attn_out + ((size_t)(b*NHEADS + head)*NHW + i0)*NSS;
  #pragma unroll 4
  for (int it = 0; it < 32; it++) {
    int e = it*256 + tid;
    int qi = e >> 7, jp = e & 127;
    float inv = sInv[qi];
    float2 p2 = *(const float2*)&sS[qi*SSTR + 2*jp];
    p2.x *= inv; p2.y *= inv;
    *(float2*)&aout[(size_t)qi*NSS + 2*jp] = p2;
    splitpack(p2.x, p2.y, sPb[qi*PPP + jp], sPs[qi*PPP + jp]);
  }
  __syncthreads();

  // ================= AV (two j-halves) =================
  {
    const int wm = wid >> 2, wn = wid & 3;   // 2 x 4
    float acc3[2][2][4];
    #pragma unroll
    for (int i=0;i<2;i++)
      #pragma unroll
      for (int j=0;j<2;j++)
        #pragma unroll
        for (int l=0;l<4;l++) acc3[i][j][l]=0.f;

    #pragma unroll 1
    for (int half = 0; half < 2; half++) {
      if (half == 1) {
        __syncthreads();
        const uint32_t* vbp = vb  + ((size_t)(b*NHEADS + head)*64)*128 + 64;
        const uint32_t* vsp = vs_ + ((size_t)(b*NHEADS + head)*64)*128 + 64;
        #pragma unroll
        for (int it = 0; it < 16; it++) {
          int e = it*256 + tid;
          int d = e >> 6, jp = e & 63;
          sVb[d*VPP + jp] = vbp[d*128 + jp];
          sVs[d*VPP + jp] = vsp[d*128 + jp];
        }
        __syncthreads();
      }
      const int p0 = half*64;
      #pragma unroll 4
      for (int ks = 0; ks < 8; ks++) {
        int k0 = ks*8;
        uint32_t ab[2][4], as_[2][4];
        #pragma unroll
        for (int mt = 0; mt < 2; mt++) {
          int q = wm*32 + mt*16 + g;
          ab[mt][0]  = sPb[q*PPP + p0 + k0 + tg];
          ab[mt][1]  = sPb[(q+8)*PPP + p0 + k0 + tg];
          ab[mt][2]  = sPb[q*PPP + p0 + k0 + tg + 4];
          ab[mt][3]  = sPb[(q+8)*PPP + p0 + k0 + tg + 4];
          as_[mt][0] = sPs[q*PPP + p0 + k0 + tg];
          as_[mt][1] = sPs[(q+8)*PPP + p0 + k0 + tg];
          as_[mt][2] = sPs[q*PPP + p0 + k0 + tg + 4];
          as_[mt][3] = sPs[(q+8)*PPP + p0 + k0 + tg + 4];
        }
        uint32_t bb[2][2], bs[2][2];
        #pragma unroll
        for (int nt = 0; nt < 2; nt++) {
          int d = wn*16 + nt*8 + g;
          bb[nt][0] = sVb[d*VPP + k0 + tg];
          bb[nt][1] = sVb[d*VPP + k0 + tg + 4];
          bs[nt][0] = sVs[d*VPP + k0 + tg];
          bs[nt][1] = sVs[d*VPP + k0 + tg + 4];
        }
        #pragma unroll
        for (int mt = 0; mt < 2; mt++)
          #pragma unroll
          for (int nt = 0; nt < 2; nt++) {
            mma16(acc3[mt][nt], ab[mt],  bb[nt]);
            mma16(acc3[mt][nt], ab[mt],  bs[nt]);
            mma16(acc3[mt][nt], as_[mt], bb[nt]);
          }
      }
    }
    #pragma unroll
    for (int mt = 0; mt < 2; mt++) {
      int q = wm*32 + mt*16 + g;
      #pragma unroll
      for (int nt = 0; nt < 2; nt++) {
        int col = wn*16 + nt*8 + 2*tg;
        *(float2*)&sO[q*OSTR + col]     = make_float2(acc3[mt][nt][0], acc3[mt][nt][1]);
        *(float2*)&sO[(q+8)*OSTR + col] = make_float2(acc3[mt][nt][2], acc3[mt][nt][3]);
      }
    }
  }
  __syncthreads();
  #pragma unroll
  for (int l = 0; l < 16; l++) {
    int e = l*256 + tid;
    int d = e >> 6, qi = e & 63;
    av[((size_t)(b*NINNER) + d*NHEADS + head)*NHW + i0 + qi] = sO[qi*OSTR + d];
  }
}

// ======================= launch =======================
extern "C" void kernel_launch(void* const* d_in, const int* in_sizes, int n_in,
                              void* d_out, int out_size) {
  const float* x    = (const float*)d_in[0];
  const float* dw1  = (const float*)d_in[1];
  const float* pw1  = (const float*)d_in[2];
  const float* relw = (const float*)d_in[3];
  const float* relh = (const float*)d_in[4];
  const float* dw2  = (const float*)d_in[5];
  const float* pw2  = (const float*)d_in[6];

  float* out  = (float*)d_out;
  float* attn = out + (size_t)NB*NINNER*NHW;

  uint32_t *t1tb, *t1ts, *t2tb, *t2ts, *kb, *ks, *vb, *vs;
  uint32_t *w1b, *w1s, *w2b, *w2s;
  float *qkvb, *avb;
  cudaGetSymbolAddress((void**)&t1tb, g_t1tb);
  cudaGetSymbolAddress((void**)&t1ts, g_t1ts);
  cudaGetSymbolAddress((void**)&qkvb, g_qkv);
  cudaGetSymbolAddress((void**)&kb,   g_kb);
  cudaGetSymbolAddress((void**)&ks,   g_ks);
  cudaGetSymbolAddress((void**)&vb,   g_vb);
  cudaGetSymbolAddress((void**)&vs,   g_vs);
  cudaGetSymbolAddress((void**)&avb,  g_av);
  cudaGetSymbolAddress((void**)&t2tb, g_t2tb);
  cudaGetSymbolAddress((void**)&t2ts, g_t2ts);
  cudaGetSymbolAddress((void**)&w1b,  g_w1b);
  cudaGetSymbolAddress((void**)&w1s,  g_w1s);
  cudaGetSymbolAddress((void**)&w2b,  g_w2b);
  cudaGetSymbolAddress((void**)&w2s,  g_w2s);

  const int mm_smem = 4*128*GP*4;  // 73728 B, 2 CTAs/SM
  cudaFuncSetAttribute(mm_bf16, cudaFuncAttributeMaxDynamicSharedMemorySize, mm_smem);
  const int at_smem = 49216*4;     // 196864 B
  cudaFuncSetAttribute(attn_k, cudaFuncAttributeMaxDynamicSharedMemorySize, at_smem);

  wsplit<<<(768*128+255)/256, 256>>>(pw1, w1b, w1s, 768*128);
  wsplit<<<(256*128+255)/256, 256>>>(pw2, w2b, w2s, 256*128);
  dw_t<<<dim3(NHW/32, 8, NB), 256>>>(x, dw1, t1tb, t1ts);
  mm_bf16<<<dim3(NHW/128, 768/128, NB), 256, mm_smem>>>(w1b, w1s, t1tb, t1ts, qkvb, 768);
  pool_split<<<1024, 256>>>(qkvb, kb, ks, vb, vs);
  attn_k<<<dim3(NHW/QT, NHEADS, NB), 256, at_smem>>>(qkvb, kb, ks, vb, vs,
                                                     relw, relh, attn, avb);
  dw_t<<<dim3(NHW/32, 8, NB), 256>>>(avb, dw2, t2tb, t2ts);
  mm_bf16<<<dim3(NHW/128, 256/128, NB), 256, mm_smem>>>(w2b, w2s, t2tb, t2ts, out, 256);
}